// round 15
// baseline (speedup 1.0000x reference)
#include <cuda_runtime.h>
#include <cuda_fp16.h>
#include <math.h>
#include <stdint.h>

#define SLEN 2048
#define HIDDEN 2880
#define NHEADS 64
#define NKV 8
#define HDIM 64
#define QDIM (NHEADS * HDIM)   /* 4096 */
#define KVDIM (NKV * HDIM)     /* 512  */

// -------------------- scratch (static device globals; no allocation) ---------
__device__ __half g_hsh[SLEN * HIDDEN];
__device__ __half g_wqh[QDIM * HIDDEN];
__device__ __half g_wkh[KVDIM * HIDDEN];
__device__ __half g_wvh[KVDIM * HIDDEN];
__device__ __half g_woh[HIDDEN * QDIM];
__device__ __half g_qh[SLEN * QDIM];     // Q pre-scaled by 0.125*log2(e)
__device__ __half g_kh[SLEN * KVDIM];
__device__ __half g_vt[KVDIM * SLEN];    // V transposed [d][t]
__device__ __half g_aoh[SLEN * QDIM];

// ---------------------------------------------------------------------------
// helpers
// ---------------------------------------------------------------------------
__device__ __forceinline__ uint32_t h2pack(float x, float y) {
    __half2 h = __floats2half2_rn(x, y);
    return *(uint32_t*)&h;
}

__device__ __forceinline__ void mma_f16(float* c, const uint32_t* a,
                                        uint32_t b0, uint32_t b1) {
    asm volatile(
        "mma.sync.aligned.m16n8k16.row.col.f32.f16.f16.f32 "
        "{%0,%1,%2,%3}, {%4,%5,%6,%7}, {%8,%9}, {%0,%1,%2,%3};"
        : "+f"(c[0]), "+f"(c[1]), "+f"(c[2]), "+f"(c[3])
        : "r"(a[0]), "r"(a[1]), "r"(a[2]), "r"(a[3]), "r"(b0), "r"(b1));
}

__device__ __forceinline__ void ldmx4(uint32_t& r0, uint32_t& r1,
                                      uint32_t& r2, uint32_t& r3,
                                      uint32_t addr) {
    asm volatile("ldmatrix.sync.aligned.m8n8.x4.shared.b16 {%0,%1,%2,%3}, [%4];"
                 : "=r"(r0), "=r"(r1), "=r"(r2), "=r"(r3) : "r"(addr));
}

#define CP_ASYNC16(dst, src)                                             \
    asm volatile("cp.async.cg.shared.global [%0], [%1], 16;"             \
                 :: "r"(dst), "l"(src))
#define CP_COMMIT() asm volatile("cp.async.commit_group;")
#define CP_WAIT0() asm volatile("cp.async.wait_group 0;")
#define CP_WAIT1() asm volatile("cp.async.wait_group 1;")

__device__ __forceinline__ uint32_t smem_u32(const void* p) {
    return (uint32_t)__cvta_generic_to_shared(p);
}

// Q pre-scale: 1/sqrt(64) * log2(e) so exp(x) == exp2(scaled dot)
#define QSCALE 0.1803368801111244f

// ============================================================================
// Fused fp32 -> fp16 conversion of all 5 tensors, 4-way unrolled (MLP=4).
// ============================================================================
#define N4_HS  (SLEN * HIDDEN / 4)
#define N4_WQ  (QDIM * HIDDEN / 4)
#define N4_WKV (KVDIM * HIDDEN / 4)
#define N4_WO  (HIDDEN * QDIM / 4)
#define N4_TOT (N4_HS + N4_WQ + 2 * N4_WKV + N4_WO)

__global__ __launch_bounds__(256) void cvt_all(
    const float4* __restrict__ hs, const float4* __restrict__ wq,
    const float4* __restrict__ wk, const float4* __restrict__ wv,
    const float4* __restrict__ wo)
{
    const int stride = gridDim.x * blockDim.x;
    for (int i0 = blockIdx.x * blockDim.x + threadIdx.x; i0 < N4_TOT;
         i0 += 4 * stride) {
#pragma unroll
        for (int u = 0; u < 4; u++) {
            int i = i0 + u * stride;
            if (i >= N4_TOT) break;
            const float4* src;
            uint2* dst;
            int off = i;
            if (off < N4_HS) {
                src = hs; dst = (uint2*)g_hsh;
            } else if ((off -= N4_HS) < N4_WQ) {
                src = wq; dst = (uint2*)g_wqh;
            } else if ((off -= N4_WQ) < N4_WKV) {
                src = wk; dst = (uint2*)g_wkh;
            } else if ((off -= N4_WKV) < N4_WKV) {
                src = wv; dst = (uint2*)g_wvh;
            } else {
                off -= N4_WKV;
                src = wo; dst = (uint2*)g_woh;
            }
            float4 v = src[off];
            dst[off] = make_uint2(h2pack(v.x, v.y), h2pack(v.z, v.w));
        }
    }
}

// ============================================================================
// fp16 GEMM: tile 256x128 (raises arithmetic intensity: 0.75x cp.async count),
// BK=32, 3-stage cp.async, 256 threads, 8 warps each 64x64 (4m x 2n layout),
// ldmatrix fragments. GLD=40 halves. smem/stage = (256+128)*40*2 = 30720B,
// 3 stages = 92160B -> 1 CTA/SM.
// ============================================================================
#define GLD 40
#define A_STG (256 * GLD)              /* 10240 halves */
#define B_STG (128 * GLD)              /*  5120 halves */
#define STG_HH (A_STG + B_STG)         /* 15360 halves per stage */
#define GEMM_SMEM (3 * STG_HH * 2)     /* 92160 bytes */

// ============================================================================
// Fused QKV GEMM. blockIdx.x: [0,32) Q (pre-scaled), [32,36) K, [36,40) V(T).
// ============================================================================
__global__ __launch_bounds__(256, 1) void qkv_gemm(
    const float* __restrict__ bq, const float* __restrict__ bk,
    const float* __restrict__ bv)
{
    extern __shared__ __half gsm[];

    const int bx = blockIdx.x;
    const int mode = (bx < 32) ? 0 : ((bx < 36) ? 1 : 2);
    const __half* Bg = (mode == 0) ? g_wqh : ((mode == 1) ? g_wkh : g_wvh);
    const float* bias = (mode == 0) ? bq : ((mode == 1) ? bk : bv);
    const int n0 = ((mode == 0) ? bx : ((mode == 1) ? bx - 32 : bx - 36)) * 128;

    const int tid  = threadIdx.x;
    const int lane = tid & 31;
    const int w    = tid >> 5;          // 0..7
    const int wm   = (w & 3) * 64;      // 4 m-warps
    const int wn   = (w >> 2) * 64;     // 2 n-warps
    const int m0   = blockIdx.y * 256;
    const int g    = lane >> 2;
    const int tg   = lane & 3;
    const int l8   = lane & 7;

    const int aoff = (wm + ((lane >> 3) & 1) * 8 + l8) * GLD + (lane >> 4) * 8;
    const int boff = (wn + (lane >> 4) * 8 + l8) * GLD + ((lane >> 3) & 1) * 8;

    float acc[4][8][4];
#pragma unroll
    for (int i = 0; i < 4; i++)
#pragma unroll
        for (int j = 0; j < 8; j++)
#pragma unroll
            for (int q = 0; q < 4; q++) acc[i][j][q] = 0.0f;

    // loader: A 256 rows x 4 chunks (4/thread), B 128 rows x 4 chunks (2/thread)
    const int lrow = tid >> 2;   // 0..63
    const int lch  = tid & 3;

    auto issue = [&](int t) {
        const int s = t % 3;
        __half* Ab = gsm + s * STG_HH;
        __half* Bb = Ab + A_STG;
        const int k0 = t * 32;
#pragma unroll
        for (int i = 0; i < 4; i++) {
            const int r = lrow + i * 64;
            CP_ASYNC16(smem_u32(&Ab[r * GLD + lch * 8]),
                       g_hsh + (size_t)(m0 + r) * HIDDEN + k0 + lch * 8);
        }
#pragma unroll
        for (int i = 0; i < 2; i++) {
            const int r = lrow + i * 64;
            CP_ASYNC16(smem_u32(&Bb[r * GLD + lch * 8]),
                       Bg + (size_t)(n0 + r) * HIDDEN + k0 + lch * 8);
        }
        CP_COMMIT();
    };

    const int KT = HIDDEN / 32;  // 90
    issue(0); issue(1);

    for (int t = 0; t < KT; t++) {
        if (t + 1 < KT) CP_WAIT1();
        else CP_WAIT0();
        __syncthreads();

        const int s = t % 3;
        const __half* Ab = gsm + s * STG_HH;
        const __half* Bb = Ab + A_STG;
        const uint32_t abase = smem_u32(&Ab[aoff]);
        const uint32_t bbase = smem_u32(&Bb[boff]);

#pragma unroll
        for (int kk = 0; kk < 2; kk++) {
            uint32_t a[4][4];
#pragma unroll
            for (int mi = 0; mi < 4; mi++)
                ldmx4(a[mi][0], a[mi][1], a[mi][2], a[mi][3],
                      abase + (mi * 16 * GLD + kk * 16) * 2);
#pragma unroll
            for (int p = 0; p < 4; p++) {
                uint32_t b00, b01, b10, b11;
                ldmx4(b00, b01, b10, b11,
                      bbase + (p * 16 * GLD + kk * 16) * 2);
#pragma unroll
                for (int mi = 0; mi < 4; mi++) {
                    mma_f16(acc[mi][2 * p],     a[mi], b00, b01);
                    mma_f16(acc[mi][2 * p + 1], a[mi], b10, b11);
                }
            }
        }
        if (t + 2 < KT) issue(t + 2);
    }

    // epilogue -> fp16 outputs (Q pre-scaled by QSCALE)
#pragma unroll
    for (int mi = 0; mi < 4; mi++) {
#pragma unroll
        for (int nj = 0; nj < 8; nj++) {
            const int col = n0 + wn + nj * 8 + 2 * tg;
            const int row = m0 + wm + mi * 16 + g;
            const float b0 = bias[col];
            const float b1 = bias[col + 1];
            float v00 = acc[mi][nj][0] + b0, v01 = acc[mi][nj][1] + b1;
            float v10 = acc[mi][nj][2] + b0, v11 = acc[mi][nj][3] + b1;
            if (mode == 0) {
                v00 *= QSCALE; v01 *= QSCALE; v10 *= QSCALE; v11 *= QSCALE;
                *(uint32_t*)&g_qh[(size_t)row * QDIM + col] = h2pack(v00, v01);
                *(uint32_t*)&g_qh[(size_t)(row + 8) * QDIM + col] = h2pack(v10, v11);
            } else if (mode == 1) {
                *(uint32_t*)&g_kh[(size_t)row * KVDIM + col] = h2pack(v00, v01);
                *(uint32_t*)&g_kh[(size_t)(row + 8) * KVDIM + col] = h2pack(v10, v11);
            } else {
                g_vt[(size_t)col * SLEN + row]           = __float2half_rn(v00);
                g_vt[(size_t)(col + 1) * SLEN + row]     = __float2half_rn(v01);
                g_vt[(size_t)col * SLEN + row + 8]       = __float2half_rn(v10);
                g_vt[(size_t)(col + 1) * SLEN + row + 8] = __float2half_rn(v11);
            }
        }
    }
}

// ============================================================================
// Output projection: fp16 A (g_aoh) x fp16 B (g_woh) -> fp32 out + bias.
// Same 256x128 tile.
// ============================================================================
__global__ __launch_bounds__(256, 1) void wo_gemm(
    const float* __restrict__ bo, float* __restrict__ C)
{
    extern __shared__ __half gsm[];

    const int tid  = threadIdx.x;
    const int lane = tid & 31;
    const int w    = tid >> 5;
    const int wm   = (w & 3) * 64;
    const int wn   = (w >> 2) * 64;
    const int m0   = blockIdx.y * 256;
    const int n0   = blockIdx.x * 128;
    const int g    = lane >> 2;
    const int tg   = lane & 3;
    const int l8   = lane & 7;

    const int aoff = (wm + ((lane >> 3) & 1) * 8 + l8) * GLD + (lane >> 4) * 8;
    const int boff = (wn + (lane >> 4) * 8 + l8) * GLD + ((lane >> 3) & 1) * 8;

    float acc[4][8][4];
#pragma unroll
    for (int i = 0; i < 4; i++)
#pragma unroll
        for (int j = 0; j < 8; j++)
#pragma unroll
            for (int q = 0; q < 4; q++) acc[i][j][q] = 0.0f;

    const int lrow = tid >> 2;
    const int lch  = tid & 3;

    auto issue = [&](int t) {
        const int s = t % 3;
        __half* Ab = gsm + s * STG_HH;
        __half* Bb = Ab + A_STG;
        const int k0 = t * 32;
#pragma unroll
        for (int i = 0; i < 4; i++) {
            const int r = lrow + i * 64;
            CP_ASYNC16(smem_u32(&Ab[r * GLD + lch * 8]),
                       g_aoh + (size_t)(m0 + r) * QDIM + k0 + lch * 8);
        }
#pragma unroll
        for (int i = 0; i < 2; i++) {
            const int r = lrow + i * 64;
            const int nrow = n0 + r;
            CP_ASYNC16(smem_u32(&Bb[r * GLD + lch * 8]),
                       g_woh + (size_t)(nrow < HIDDEN ? nrow : 0) * QDIM + k0 + lch * 8);
        }
        CP_COMMIT();
    };

    const int KT = QDIM / 32;  // 128
    issue(0); issue(1);

    for (int t = 0; t < KT; t++) {
        if (t + 1 < KT) CP_WAIT1();
        else CP_WAIT0();
        __syncthreads();

        const int s = t % 3;
        const __half* Ab = gsm + s * STG_HH;
        const __half* Bb = Ab + A_STG;
        const uint32_t abase = smem_u32(&Ab[aoff]);
        const uint32_t bbase = smem_u32(&Bb[boff]);

#pragma unroll
        for (int kk = 0; kk < 2; kk++) {
            uint32_t a[4][4];
#pragma unroll
            for (int mi = 0; mi < 4; mi++)
                ldmx4(a[mi][0], a[mi][1], a[mi][2], a[mi][3],
                      abase + (mi * 16 * GLD + kk * 16) * 2);
#pragma unroll
            for (int p = 0; p < 4; p++) {
                uint32_t b00, b01, b10, b11;
                ldmx4(b00, b01, b10, b11,
                      bbase + (p * 16 * GLD + kk * 16) * 2);
#pragma unroll
                for (int mi = 0; mi < 4; mi++) {
                    mma_f16(acc[mi][2 * p],     a[mi], b00, b01);
                    mma_f16(acc[mi][2 * p + 1], a[mi], b10, b11);
                }
            }
        }
        if (t + 2 < KT) issue(t + 2);
    }

#pragma unroll
    for (int mi = 0; mi < 4; mi++) {
#pragma unroll
        for (int nj = 0; nj < 8; nj++) {
            const int col = n0 + wn + nj * 8 + 2 * tg;
            if (col < HIDDEN) {
                const float b0 = bo[col];
                const float b1 = bo[col + 1];
                const int row = m0 + wm + mi * 16 + g;
                *(float2*)(C + (size_t)row * HIDDEN + col) =
                    make_float2(acc[mi][nj][0] + b0, acc[mi][nj][1] + b1);
                *(float2*)(C + (size_t)(row + 8) * HIDDEN + col) =
                    make_float2(acc[mi][nj][2] + b0, acc[mi][nj][3] + b1);
            }
        }
    }
}

// ============================================================================
// FP16 flash attention (R14 state): BM=128, 8 warps, no-max exp2 softmax,
// 3-buffer KV pipeline, single barrier/tile, heavy-qb-first, diag-only mask.
// ============================================================================
#define FLD 72

__global__ __launch_bounds__(256, 2) void flash_f16()
{
    __shared__ __half Kh[3][64 * FLD];
    __shared__ __half Vh[3][64 * FLD];

    const int h    = blockIdx.y;
    const int qb   = gridDim.x - 1 - blockIdx.x;
    const int kvh  = h >> 3;
    const int tid  = threadIdx.x;
    const int wid  = tid >> 5;
    const int lane = tid & 31;
    const int g    = lane >> 2;
    const int tg   = lane & 3;
    const int l8   = lane & 7;
    const int r0   = qb * 128;
    const int wr   = wid * 16;

    const int qoff  = ((wr & 63) + ((lane >> 3) & 1) * 8 + l8) * FLD + (lane >> 4) * 8;
    const int kvoff = ((lane >> 4) * 8 + l8) * FLD + ((lane >> 3) & 1) * 8;

#pragma unroll
    for (int i = 0; i < 4; i++) {
        const int idx = tid + i * 256;
        const int r = idx >> 3, ch = idx & 7;
        __half* dst = (r < 64) ? &Kh[0][r * FLD + ch * 8]
                               : &Vh[0][(r - 64) * FLD + ch * 8];
        CP_ASYNC16(smem_u32(dst),
                   g_qh + (size_t)(r0 + r) * QDIM + h * HDIM + ch * 8);
    }
    CP_COMMIT();
    CP_WAIT0();
    __syncthreads();

    uint32_t qf[4][4];
    {
        const __half* Qb = (wid < 4) ? &Kh[0][0] : &Vh[0][0];
        const uint32_t qbase = smem_u32(&Qb[qoff]);
#pragma unroll
        for (int kk = 0; kk < 4; kk++)
            ldmx4(qf[kk][0], qf[kk][1], qf[kk][2], qf[kk][3],
                  qbase + kk * 16 * 2);
    }
    __syncthreads();

    const int lr = tid >> 3;
    const int lc = tid & 7;

    auto issue_kv = [&](int j, int buf) {
        const int t0 = j * 64;
#pragma unroll
        for (int i = 0; i < 2; i++) {
            const int r = lr + i * 32;
            CP_ASYNC16(smem_u32(&Kh[buf][r * FLD + lc * 8]),
                       g_kh + (size_t)(t0 + r) * KVDIM + kvh * HDIM + lc * 8);
            CP_ASYNC16(smem_u32(&Vh[buf][r * FLD + lc * 8]),
                       g_vt + (size_t)(kvh * HDIM + r) * SLEN + t0 + lc * 8);
        }
        CP_COMMIT();
    };

    float o[8][4];
#pragma unroll
    for (int nj = 0; nj < 8; nj++)
#pragma unroll
        for (int c = 0; c < 4; c++) o[nj][c] = 0.0f;
    float l_lo = 0.0f, l_hi = 0.0f;

    const int jmax = 2 * qb + 1;
    issue_kv(0, 0);
    if (1 <= jmax) issue_kv(1, 1);

    for (int j = 0; j <= jmax; j++) {
        if (j < jmax) CP_WAIT1();
        else CP_WAIT0();
        __syncthreads();

        if (j + 2 <= jmax) issue_kv(j + 2, (j + 2) % 3);

        const int buf = j % 3;
        const int t0 = j * 64;
        if (t0 <= r0 + wr + 15) {
            const uint32_t kbase = smem_u32(&Kh[buf][kvoff]);
            const uint32_t vbase = smem_u32(&Vh[buf][kvoff]);

            float s[8][4];
#pragma unroll
            for (int nj = 0; nj < 8; nj++)
#pragma unroll
                for (int c = 0; c < 4; c++) s[nj][c] = 0.0f;
#pragma unroll
            for (int kk = 0; kk < 4; kk++) {
#pragma unroll
                for (int p = 0; p < 4; p++) {
                    uint32_t b00, b01, b10, b11;
                    ldmx4(b00, b01, b10, b11,
                          kbase + (p * 16 * FLD + kk * 16) * 2);
                    mma_f16(s[2 * p],     qf[kk], b00, b01);
                    mma_f16(s[2 * p + 1], qf[kk], b10, b11);
                }
            }

            if (t0 + 63 > r0 + wr) {
                const int row_lo = r0 + wr + g;
                const int row_hi = row_lo + 8;
#pragma unroll
                for (int nj = 0; nj < 8; nj++) {
                    const int cb = t0 + nj * 8 + 2 * tg;
                    if (cb     > row_lo) s[nj][0] = -1e30f;
                    if (cb + 1 > row_lo) s[nj][1] = -1e30f;
                    if (cb     > row_hi) s[nj][2] = -1e30f;
                    if (cb + 1 > row_hi) s[nj][3] = -1e30f;
                }
            }

            float sum_lo = 0.0f, sum_hi = 0.0f;
#pragma unroll
            for (int nj = 0; nj < 8; nj++) {
                s[nj][0] = exp2f(s[nj][0]);
                s[nj][1] = exp2f(s[nj][1]);
                s[nj][2] = exp2f(s[nj][2]);
                s[nj][3] = exp2f(s[nj][3]);
                sum_lo += s[nj][0] + s[nj][1];
                sum_hi += s[nj][2] + s[nj][3];
            }
            l_lo += sum_lo;
            l_hi += sum_hi;

#pragma unroll
            for (int kk = 0; kk < 4; kk++) {
                uint32_t pa[4];
                pa[0] = h2pack(s[2 * kk][0],     s[2 * kk][1]);
                pa[1] = h2pack(s[2 * kk][2],     s[2 * kk][3]);
                pa[2] = h2pack(s[2 * kk + 1][0], s[2 * kk + 1][1]);
                pa[3] = h2pack(s[2 * kk + 1][2], s[2 * kk + 1][3]);
#pragma unroll
                for (int p = 0; p < 4; p++) {
                    uint32_t b00, b01, b10, b11;
                    ldmx4(b00, b01, b10, b11,
                          vbase + (p * 16 * FLD + kk * 16) * 2);
                    mma_f16(o[2 * p],     pa, b00, b01);
                    mma_f16(o[2 * p + 1], pa, b10, b11);
                }
            }
        }
    }

    l_lo += __shfl_xor_sync(0xffffffffu, l_lo, 1);
    l_lo += __shfl_xor_sync(0xffffffffu, l_lo, 2);
    l_hi += __shfl_xor_sync(0xffffffffu, l_hi, 1);
    l_hi += __shfl_xor_sync(0xffffffffu, l_hi, 2);
    const float inv_lo = 1.0f / l_lo;
    const float inv_hi = 1.0f / l_hi;
#pragma unroll
    for (int nj = 0; nj < 8; nj++) {
        const int col = h * HDIM + nj * 8 + 2 * tg;
        *(uint32_t*)&g_aoh[(size_t)(r0 + wr + g) * QDIM + col] =
            h2pack(o[nj][0] * inv_lo, o[nj][1] * inv_lo);
        *(uint32_t*)&g_aoh[(size_t)(r0 + wr + g + 8) * QDIM + col] =
            h2pack(o[nj][2] * inv_hi, o[nj][3] * inv_hi);
    }
}

// ============================================================================
// launch
// ============================================================================
extern "C" void kernel_launch(void* const* d_in, const int* in_sizes, int n_in,
                              void* d_out, int out_size)
{
    (void)in_sizes; (void)n_in; (void)out_size;
    const float* hs = (const float*)d_in[0];
    const float* Wq = (const float*)d_in[2];
    const float* bq = (const float*)d_in[3];
    const float* Wk = (const float*)d_in[4];
    const float* bk = (const float*)d_in[5];
    const float* Wv = (const float*)d_in[6];
    const float* bv = (const float*)d_in[7];
    const float* Wo = (const float*)d_in[8];
    const float* bo = (const float*)d_in[9];
    float* out = (float*)d_out;

    static bool attr_set = false;
    if (!attr_set) {
        cudaFuncSetAttribute(qkv_gemm,
                             cudaFuncAttributeMaxDynamicSharedMemorySize, GEMM_SMEM);
        cudaFuncSetAttribute(wo_gemm,
                             cudaFuncAttributeMaxDynamicSharedMemorySize, GEMM_SMEM);
        attr_set = true;
    }

    cvt_all<<<2048, 256>>>((const float4*)hs, (const float4*)Wq,
                           (const float4*)Wk, (const float4*)Wv,
                           (const float4*)Wo);
    qkv_gemm<<<dim3(40, SLEN / 256), 256, GEMM_SMEM>>>(bq, bk, bv);
    flash_f16<<<dim3(SLEN / 128, NHEADS), 256>>>();
    wo_gemm<<<dim3((HIDDEN + 127) / 128, SLEN / 256), 256, GEMM_SMEM>>>(bo, out);
}

// round 16
// speedup vs baseline: 1.1876x; 1.1876x over previous
#include <cuda_runtime.h>
#include <cuda_fp16.h>
#include <math.h>
#include <stdint.h>

#define SLEN 2048
#define HIDDEN 2880
#define NHEADS 64
#define NKV 8
#define HDIM 64
#define QDIM (NHEADS * HDIM)   /* 4096 */
#define KVDIM (NKV * HDIM)     /* 512  */

// -------------------- scratch (static device globals; no allocation) ---------
__device__ __half g_hsh[SLEN * HIDDEN];
__device__ __half g_wqh[QDIM * HIDDEN];
__device__ __half g_wkh[KVDIM * HIDDEN];
__device__ __half g_wvh[KVDIM * HIDDEN];
__device__ __half g_woh[HIDDEN * QDIM];
__device__ __half g_qh[SLEN * QDIM];     // Q pre-scaled by 0.125*log2(e)
__device__ __half g_kh[SLEN * KVDIM];
__device__ __half g_vt[KVDIM * SLEN];    // V transposed [d][t]
__device__ __half g_aoh[SLEN * QDIM];

// ---------------------------------------------------------------------------
// helpers
// ---------------------------------------------------------------------------
__device__ __forceinline__ uint32_t h2pack(float x, float y) {
    __half2 h = __floats2half2_rn(x, y);
    return *(uint32_t*)&h;
}

__device__ __forceinline__ void mma_f16(float* c, const uint32_t* a,
                                        uint32_t b0, uint32_t b1) {
    asm volatile(
        "mma.sync.aligned.m16n8k16.row.col.f32.f16.f16.f32 "
        "{%0,%1,%2,%3}, {%4,%5,%6,%7}, {%8,%9}, {%0,%1,%2,%3};"
        : "+f"(c[0]), "+f"(c[1]), "+f"(c[2]), "+f"(c[3])
        : "r"(a[0]), "r"(a[1]), "r"(a[2]), "r"(a[3]), "r"(b0), "r"(b1));
}

__device__ __forceinline__ void ldmx4(uint32_t& r0, uint32_t& r1,
                                      uint32_t& r2, uint32_t& r3,
                                      uint32_t addr) {
    asm volatile("ldmatrix.sync.aligned.m8n8.x4.shared.b16 {%0,%1,%2,%3}, [%4];"
                 : "=r"(r0), "=r"(r1), "=r"(r2), "=r"(r3) : "r"(addr));
}

#define CP_ASYNC16(dst, src)                                             \
    asm volatile("cp.async.cg.shared.global [%0], [%1], 16;"             \
                 :: "r"(dst), "l"(src))
#define CP_COMMIT() asm volatile("cp.async.commit_group;")
#define CP_WAIT0() asm volatile("cp.async.wait_group 0;")
#define CP_WAIT1() asm volatile("cp.async.wait_group 1;")
#define CP_WAIT2() asm volatile("cp.async.wait_group 2;")

__device__ __forceinline__ uint32_t smem_u32(const void* p) {
    return (uint32_t)__cvta_generic_to_shared(p);
}

// Q pre-scale: 1/sqrt(64) * log2(e) so exp(x) == exp2(scaled dot)
#define QSCALE 0.1803368801111244f

// ============================================================================
// Fused fp32 -> fp16 conversion of all 5 tensors, 4-way unrolled (MLP=4).
// ============================================================================
#define N4_HS  (SLEN * HIDDEN / 4)
#define N4_WQ  (QDIM * HIDDEN / 4)
#define N4_WKV (KVDIM * HIDDEN / 4)
#define N4_WO  (HIDDEN * QDIM / 4)
#define N4_TOT (N4_HS + N4_WQ + 2 * N4_WKV + N4_WO)

__global__ __launch_bounds__(256) void cvt_all(
    const float4* __restrict__ hs, const float4* __restrict__ wq,
    const float4* __restrict__ wk, const float4* __restrict__ wv,
    const float4* __restrict__ wo)
{
    const int stride = gridDim.x * blockDim.x;
    for (int i0 = blockIdx.x * blockDim.x + threadIdx.x; i0 < N4_TOT;
         i0 += 4 * stride) {
#pragma unroll
        for (int u = 0; u < 4; u++) {
            int i = i0 + u * stride;
            if (i >= N4_TOT) break;
            const float4* src;
            uint2* dst;
            int off = i;
            if (off < N4_HS) {
                src = hs; dst = (uint2*)g_hsh;
            } else if ((off -= N4_HS) < N4_WQ) {
                src = wq; dst = (uint2*)g_wqh;
            } else if ((off -= N4_WQ) < N4_WKV) {
                src = wk; dst = (uint2*)g_wkh;
            } else if ((off -= N4_WKV) < N4_WKV) {
                src = wv; dst = (uint2*)g_wvh;
            } else {
                off -= N4_WKV;
                src = wo; dst = (uint2*)g_woh;
            }
            float4 v = src[off];
            dst[off] = make_uint2(h2pack(v.x, v.y), h2pack(v.z, v.w));
        }
    }
}

// ============================================================================
// fp16 GEMM (R14/R10 proven config): tile 128x128, BK=32, 4-stage cp.async,
// 256 threads, 8 warps each 32x64, ldmatrix fragments. GLD=40 halves.
// ============================================================================
#define GLD 40
#define STG_H (128 * GLD)
#define GEMM_SMEM (4 * 2 * STG_H * 2)  /* 81920 bytes */

// ============================================================================
// Fused QKV GEMM. blockIdx.x: [0,32) Q (pre-scaled), [32,36) K, [36,40) V(T).
// ============================================================================
__global__ __launch_bounds__(256, 2) void qkv_gemm(
    const float* __restrict__ bq, const float* __restrict__ bk,
    const float* __restrict__ bv)
{
    extern __shared__ __half gsm[];

    const int bx = blockIdx.x;
    const int mode = (bx < 32) ? 0 : ((bx < 36) ? 1 : 2);
    const __half* Bg = (mode == 0) ? g_wqh : ((mode == 1) ? g_wkh : g_wvh);
    const float* bias = (mode == 0) ? bq : ((mode == 1) ? bk : bv);
    const int n0 = ((mode == 0) ? bx : ((mode == 1) ? bx - 32 : bx - 36)) * 128;

    const int tid  = threadIdx.x;
    const int lane = tid & 31;
    const int w    = tid >> 5;
    const int wm   = (w & 3) * 32;
    const int wn   = (w >> 2) * 64;
    const int m0   = blockIdx.y * 128;
    const int g    = lane >> 2;
    const int tg   = lane & 3;
    const int l8   = lane & 7;

    const int aoff = (wm + ((lane >> 3) & 1) * 8 + l8) * GLD + (lane >> 4) * 8;
    const int boff = (wn + (lane >> 4) * 8 + l8) * GLD + ((lane >> 3) & 1) * 8;

    float acc[2][8][4];
#pragma unroll
    for (int i = 0; i < 2; i++)
#pragma unroll
        for (int j = 0; j < 8; j++)
#pragma unroll
            for (int q = 0; q < 4; q++) acc[i][j][q] = 0.0f;

    const int lrow = tid >> 2;   // 0..63
    const int lch  = tid & 3;

    auto issue = [&](int t) {
        const int s = t & 3;
        __half* Ab = gsm + s * (2 * STG_H);
        __half* Bb = Ab + STG_H;
        const int k0 = t * 32;
#pragma unroll
        for (int i = 0; i < 2; i++) {
            const int r = lrow + i * 64;
            CP_ASYNC16(smem_u32(&Ab[r * GLD + lch * 8]),
                       g_hsh + (size_t)(m0 + r) * HIDDEN + k0 + lch * 8);
            CP_ASYNC16(smem_u32(&Bb[r * GLD + lch * 8]),
                       Bg + (size_t)(n0 + r) * HIDDEN + k0 + lch * 8);
        }
        CP_COMMIT();
    };

    const int KT = HIDDEN / 32;  // 90
    issue(0); issue(1); issue(2);

    for (int t = 0; t < KT; t++) {
        const int rem = KT - 1 - t;
        if (rem >= 2) CP_WAIT2();
        else if (rem == 1) CP_WAIT1();
        else CP_WAIT0();
        __syncthreads();

        const int s = t & 3;
        const __half* Ab = gsm + s * (2 * STG_H);
        const __half* Bb = Ab + STG_H;
        const uint32_t abase = smem_u32(&Ab[aoff]);
        const uint32_t bbase = smem_u32(&Bb[boff]);

#pragma unroll
        for (int kk = 0; kk < 2; kk++) {
            uint32_t a[2][4];
#pragma unroll
            for (int mi = 0; mi < 2; mi++)
                ldmx4(a[mi][0], a[mi][1], a[mi][2], a[mi][3],
                      abase + (mi * 16 * GLD + kk * 16) * 2);
#pragma unroll
            for (int p = 0; p < 4; p++) {
                uint32_t b00, b01, b10, b11;
                ldmx4(b00, b01, b10, b11,
                      bbase + (p * 16 * GLD + kk * 16) * 2);
                mma_f16(acc[0][2 * p],     a[0], b00, b01);
                mma_f16(acc[0][2 * p + 1], a[0], b10, b11);
                mma_f16(acc[1][2 * p],     a[1], b00, b01);
                mma_f16(acc[1][2 * p + 1], a[1], b10, b11);
            }
        }
        if (t + 3 < KT) issue(t + 3);
    }

    // epilogue -> fp16 outputs (Q pre-scaled by QSCALE)
#pragma unroll
    for (int mi = 0; mi < 2; mi++) {
#pragma unroll
        for (int nj = 0; nj < 8; nj++) {
            const int col = n0 + wn + nj * 8 + 2 * tg;
            const int row = m0 + wm + mi * 16 + g;
            const float b0 = bias[col];
            const float b1 = bias[col + 1];
            float v00 = acc[mi][nj][0] + b0, v01 = acc[mi][nj][1] + b1;
            float v10 = acc[mi][nj][2] + b0, v11 = acc[mi][nj][3] + b1;
            if (mode == 0) {
                v00 *= QSCALE; v01 *= QSCALE; v10 *= QSCALE; v11 *= QSCALE;
                *(uint32_t*)&g_qh[(size_t)row * QDIM + col] = h2pack(v00, v01);
                *(uint32_t*)&g_qh[(size_t)(row + 8) * QDIM + col] = h2pack(v10, v11);
            } else if (mode == 1) {
                *(uint32_t*)&g_kh[(size_t)row * KVDIM + col] = h2pack(v00, v01);
                *(uint32_t*)&g_kh[(size_t)(row + 8) * KVDIM + col] = h2pack(v10, v11);
            } else {
                g_vt[(size_t)col * SLEN + row]           = __float2half_rn(v00);
                g_vt[(size_t)(col + 1) * SLEN + row]     = __float2half_rn(v01);
                g_vt[(size_t)col * SLEN + row + 8]       = __float2half_rn(v10);
                g_vt[(size_t)(col + 1) * SLEN + row + 8] = __float2half_rn(v11);
            }
        }
    }
}

// ============================================================================
// Output projection: fp16 A (g_aoh) x fp16 B (g_woh) -> fp32 out + bias.
// ============================================================================
__global__ __launch_bounds__(256, 2) void wo_gemm(
    const float* __restrict__ bo, float* __restrict__ C)
{
    extern __shared__ __half gsm[];

    const int tid  = threadIdx.x;
    const int lane = tid & 31;
    const int w    = tid >> 5;
    const int wm   = (w & 3) * 32;
    const int wn   = (w >> 2) * 64;
    const int m0   = blockIdx.y * 128;
    const int n0   = blockIdx.x * 128;
    const int g    = lane >> 2;
    const int tg   = lane & 3;
    const int l8   = lane & 7;

    const int aoff = (wm + ((lane >> 3) & 1) * 8 + l8) * GLD + (lane >> 4) * 8;
    const int boff = (wn + (lane >> 4) * 8 + l8) * GLD + ((lane >> 3) & 1) * 8;

    float acc[2][8][4];
#pragma unroll
    for (int i = 0; i < 2; i++)
#pragma unroll
        for (int j = 0; j < 8; j++)
#pragma unroll
            for (int q = 0; q < 4; q++) acc[i][j][q] = 0.0f;

    const int lrow = tid >> 2;
    const int lch  = tid & 3;

    auto issue = [&](int t) {
        const int s = t & 3;
        __half* Ab = gsm + s * (2 * STG_H);
        __half* Bb = Ab + STG_H;
        const int k0 = t * 32;
#pragma unroll
        for (int i = 0; i < 2; i++) {
            const int r = lrow + i * 64;
            CP_ASYNC16(smem_u32(&Ab[r * GLD + lch * 8]),
                       g_aoh + (size_t)(m0 + r) * QDIM + k0 + lch * 8);
            const int nrow = n0 + r;
            CP_ASYNC16(smem_u32(&Bb[r * GLD + lch * 8]),
                       g_woh + (size_t)(nrow < HIDDEN ? nrow : 0) * QDIM + k0 + lch * 8);
        }
        CP_COMMIT();
    };

    const int KT = QDIM / 32;  // 128
    issue(0); issue(1); issue(2);

    for (int t = 0; t < KT; t++) {
        const int rem = KT - 1 - t;
        if (rem >= 2) CP_WAIT2();
        else if (rem == 1) CP_WAIT1();
        else CP_WAIT0();
        __syncthreads();

        const int s = t & 3;
        const __half* Ab = gsm + s * (2 * STG_H);
        const __half* Bb = Ab + STG_H;
        const uint32_t abase = smem_u32(&Ab[aoff]);
        const uint32_t bbase = smem_u32(&Bb[boff]);

#pragma unroll
        for (int kk = 0; kk < 2; kk++) {
            uint32_t a[2][4];
#pragma unroll
            for (int mi = 0; mi < 2; mi++)
                ldmx4(a[mi][0], a[mi][1], a[mi][2], a[mi][3],
                      abase + (mi * 16 * GLD + kk * 16) * 2);
#pragma unroll
            for (int p = 0; p < 4; p++) {
                uint32_t b00, b01, b10, b11;
                ldmx4(b00, b01, b10, b11,
                      bbase + (p * 16 * GLD + kk * 16) * 2);
                mma_f16(acc[0][2 * p],     a[0], b00, b01);
                mma_f16(acc[0][2 * p + 1], a[0], b10, b11);
                mma_f16(acc[1][2 * p],     a[1], b00, b01);
                mma_f16(acc[1][2 * p + 1], a[1], b10, b11);
            }
        }
        if (t + 3 < KT) issue(t + 3);
    }

#pragma unroll
    for (int mi = 0; mi < 2; mi++) {
#pragma unroll
        for (int nj = 0; nj < 8; nj++) {
            const int col = n0 + wn + nj * 8 + 2 * tg;
            if (col < HIDDEN) {
                const float b0 = bo[col];
                const float b1 = bo[col + 1];
                const int row = m0 + wm + mi * 16 + g;
                *(float2*)(C + (size_t)row * HIDDEN + col) =
                    make_float2(acc[mi][nj][0] + b0, acc[mi][nj][1] + b1);
                *(float2*)(C + (size_t)(row + 8) * HIDDEN + col) =
                    make_float2(acc[mi][nj][2] + b0, acc[mi][nj][3] + b1);
            }
        }
    }
}

// ============================================================================
// FP16 flash attention, GQA-paired: one CTA = 2 heads sharing a kv-head,
// BM=128 per head, 512 threads (16 warps: 0-7 head A, 8-15 head B).
// Halves KV cp.async traffic (the LSU-floor term). No-max exp2 softmax,
// 3-buffer KV pipeline, single barrier per tile, heavy-qb-first,
// diagonal-only mask, Q pre-scaled by 0.125*log2e.
// ============================================================================
#define FLD 72

__global__ __launch_bounds__(512, 1) void flash_f16()
{
    __shared__ __half Kh[3][64 * FLD];
    __shared__ __half Vh[3][64 * FLD];

    const int pair = blockIdx.y;                  // 0..31
    const int qb   = gridDim.x - 1 - blockIdx.x;  // heavy first, 0..15
    const int kvh  = pair >> 2;
    const int tid  = threadIdx.x;
    const int wid  = tid >> 5;                    // 0..15
    const int lane = tid & 31;
    const int g    = lane >> 2;
    const int tg   = lane & 3;
    const int l8   = lane & 7;
    const int r0   = qb * 128;
    const int hsel = wid >> 3;                    // 0 or 1
    const int h    = pair * 2 + hsel;
    const int wr   = (wid & 7) * 16;              // 0..112 within the head's 128 rows

    const int qoff  = ((wr & 63) + ((lane >> 3) & 1) * 8 + l8) * FLD + (lane >> 4) * 8;
    const int kvoff = ((lane >> 4) * 8 + l8) * FLD + ((lane >> 3) & 1) * 8;

    // ---- stage Q: 2 heads x 128 rows x 8 chunks = 2048 items, 512 thr x 4 ----
    // head0 rows -> Kh[0](0-63)+Vh[0](64-127); head1 -> Kh[1]+Vh[1]
#pragma unroll
    for (int i = 0; i < 4; i++) {
        const int idx = tid + i * 512;
        const int hh = idx >> 10;            // 0..1
        const int r  = (idx >> 3) & 127;     // 0..127
        const int ch = idx & 7;
        __half* dst = (r < 64) ? &Kh[hh][r * FLD + ch * 8]
                               : &Vh[hh][(r - 64) * FLD + ch * 8];
        CP_ASYNC16(smem_u32(dst),
                   g_qh + (size_t)(r0 + r) * QDIM + (pair * 2 + hh) * HDIM + ch * 8);
    }
    CP_COMMIT();
    CP_WAIT0();
    __syncthreads();

    uint32_t qf[4][4];
    {
        const __half* Qb = ((wid & 7) < 4) ? &Kh[hsel][0] : &Vh[hsel][0];
        const uint32_t qbase = smem_u32(&Qb[qoff]);
#pragma unroll
        for (int kk = 0; kk < 4; kk++)
            ldmx4(qf[kk][0], qf[kk][1], qf[kk][2], qf[kk][3],
                  qbase + kk * 16 * 2);
    }
    __syncthreads();   // Q lifted; KV pipeline may reuse all buffers

    // KV loader: 64 rows x 8 chunks = 512 items each for K and V; 1 per thread
    const int lr = tid >> 3;   // 0..63
    const int lc = tid & 7;

    auto issue_kv = [&](int j, int buf) {
        const int t0 = j * 64;
        CP_ASYNC16(smem_u32(&Kh[buf][lr * FLD + lc * 8]),
                   g_kh + (size_t)(t0 + lr) * KVDIM + kvh * HDIM + lc * 8);
        CP_ASYNC16(smem_u32(&Vh[buf][lr * FLD + lc * 8]),
                   g_vt + (size_t)(kvh * HDIM + lr) * SLEN + t0 + lc * 8);
        CP_COMMIT();
    };

    float o[8][4];
#pragma unroll
    for (int nj = 0; nj < 8; nj++)
#pragma unroll
        for (int c = 0; c < 4; c++) o[nj][c] = 0.0f;
    float l_lo = 0.0f, l_hi = 0.0f;

    const int jmax = 2 * qb + 1;
    issue_kv(0, 0);
    if (1 <= jmax) issue_kv(1, 1);

    for (int j = 0; j <= jmax; j++) {
        if (j < jmax) CP_WAIT1();
        else CP_WAIT0();
        __syncthreads();

        if (j + 2 <= jmax) issue_kv(j + 2, (j + 2) % 3);

        const int buf = j % 3;
        const int t0 = j * 64;
        if (t0 <= r0 + wr + 15) {
            const uint32_t kbase = smem_u32(&Kh[buf][kvoff]);
            const uint32_t vbase = smem_u32(&Vh[buf][kvoff]);

            // ---- S = Q . K^T (log2 domain) ----
            float s[8][4];
#pragma unroll
            for (int nj = 0; nj < 8; nj++)
#pragma unroll
                for (int c = 0; c < 4; c++) s[nj][c] = 0.0f;
#pragma unroll
            for (int kk = 0; kk < 4; kk++) {
#pragma unroll
                for (int p = 0; p < 4; p++) {
                    uint32_t b00, b01, b10, b11;
                    ldmx4(b00, b01, b10, b11,
                          kbase + (p * 16 * FLD + kk * 16) * 2);
                    mma_f16(s[2 * p],     qf[kk], b00, b01);
                    mma_f16(s[2 * p + 1], qf[kk], b10, b11);
                }
            }

            // ---- causal mask (diagonal tiles only) ----
            if (t0 + 63 > r0 + wr) {
                const int row_lo = r0 + wr + g;
                const int row_hi = row_lo + 8;
#pragma unroll
                for (int nj = 0; nj < 8; nj++) {
                    const int cb = t0 + nj * 8 + 2 * tg;
                    if (cb     > row_lo) s[nj][0] = -1e30f;
                    if (cb + 1 > row_lo) s[nj][1] = -1e30f;
                    if (cb     > row_hi) s[nj][2] = -1e30f;
                    if (cb + 1 > row_hi) s[nj][3] = -1e30f;
                }
            }

            // ---- no-max softmax: P = exp2(S) ----
            float sum_lo = 0.0f, sum_hi = 0.0f;
#pragma unroll
            for (int nj = 0; nj < 8; nj++) {
                s[nj][0] = exp2f(s[nj][0]);
                s[nj][1] = exp2f(s[nj][1]);
                s[nj][2] = exp2f(s[nj][2]);
                s[nj][3] = exp2f(s[nj][3]);
                sum_lo += s[nj][0] + s[nj][1];
                sum_hi += s[nj][2] + s[nj][3];
            }
            l_lo += sum_lo;
            l_hi += sum_hi;

            // ---- O += P . V ----
#pragma unroll
            for (int kk = 0; kk < 4; kk++) {
                uint32_t pa[4];
                pa[0] = h2pack(s[2 * kk][0],     s[2 * kk][1]);
                pa[1] = h2pack(s[2 * kk][2],     s[2 * kk][3]);
                pa[2] = h2pack(s[2 * kk + 1][0], s[2 * kk + 1][1]);
                pa[3] = h2pack(s[2 * kk + 1][2], s[2 * kk + 1][3]);
#pragma unroll
                for (int p = 0; p < 4; p++) {
                    uint32_t b00, b01, b10, b11;
                    ldmx4(b00, b01, b10, b11,
                          vbase + (p * 16 * FLD + kk * 16) * 2);
                    mma_f16(o[2 * p],     pa, b00, b01);
                    mma_f16(o[2 * p + 1], pa, b10, b11);
                }
            }
        }
    }

    // ---- reduce l across the quad, normalize, write fp16 ----
    l_lo += __shfl_xor_sync(0xffffffffu, l_lo, 1);
    l_lo += __shfl_xor_sync(0xffffffffu, l_lo, 2);
    l_hi += __shfl_xor_sync(0xffffffffu, l_hi, 1);
    l_hi += __shfl_xor_sync(0xffffffffu, l_hi, 2);
    const float inv_lo = 1.0f / l_lo;
    const float inv_hi = 1.0f / l_hi;
#pragma unroll
    for (int nj = 0; nj < 8; nj++) {
        const int col = h * HDIM + nj * 8 + 2 * tg;
        *(uint32_t*)&g_aoh[(size_t)(r0 + wr + g) * QDIM + col] =
            h2pack(o[nj][0] * inv_lo, o[nj][1] * inv_lo);
        *(uint32_t*)&g_aoh[(size_t)(r0 + wr + g + 8) * QDIM + col] =
            h2pack(o[nj][2] * inv_hi, o[nj][3] * inv_hi);
    }
}

// ============================================================================
// launch
// ============================================================================
extern "C" void kernel_launch(void* const* d_in, const int* in_sizes, int n_in,
                              void* d_out, int out_size)
{
    (void)in_sizes; (void)n_in; (void)out_size;
    const float* hs = (const float*)d_in[0];
    const float* Wq = (const float*)d_in[2];
    const float* bq = (const float*)d_in[3];
    const float* Wk = (const float*)d_in[4];
    const float* bk = (const float*)d_in[5];
    const float* Wv = (const float*)d_in[6];
    const float* bv = (const float*)d_in[7];
    const float* Wo = (const float*)d_in[8];
    const float* bo = (const float*)d_in[9];
    float* out = (float*)d_out;

    static bool attr_set = false;
    if (!attr_set) {
        cudaFuncSetAttribute(qkv_gemm,
                             cudaFuncAttributeMaxDynamicSharedMemorySize, GEMM_SMEM);
        cudaFuncSetAttribute(wo_gemm,
                             cudaFuncAttributeMaxDynamicSharedMemorySize, GEMM_SMEM);
        attr_set = true;
    }

    cvt_all<<<2048, 256>>>((const float4*)hs, (const float4*)Wq,
                           (const float4*)Wk, (const float4*)Wv,
                           (const float4*)Wo);
    qkv_gemm<<<dim3(40, SLEN / 128), 256, GEMM_SMEM>>>(bq, bk, bv);
    flash_f16<<<dim3(SLEN / 128, NHEADS / 2), 512>>>();
    wo_gemm<<<dim3((HIDDEN + 127) / 128, SLEN / 128), 256, GEMM_SMEM>>>(bo, out);
}

// round 17
// speedup vs baseline: 1.2790x; 1.0770x over previous
#include <cuda_runtime.h>
#include <cuda_fp16.h>
#include <math.h>
#include <stdint.h>

#define SLEN 2048
#define HIDDEN 2880
#define NHEADS 64
#define NKV 8
#define HDIM 64
#define QDIM (NHEADS * HDIM)   /* 4096 */
#define KVDIM (NKV * HDIM)     /* 512  */

// -------------------- scratch (static device globals; no allocation) ---------
__device__ __half g_hsh[SLEN * HIDDEN];
__device__ __half g_wqh[QDIM * HIDDEN];
__device__ __half g_wkh[KVDIM * HIDDEN];
__device__ __half g_wvh[KVDIM * HIDDEN];
__device__ __half g_woh[HIDDEN * QDIM];
__device__ __half g_qh[SLEN * QDIM];     // Q pre-scaled by 0.125*log2(e)
__device__ __half g_kh[SLEN * KVDIM];
__device__ __half g_vt[KVDIM * SLEN];    // V transposed [d][t]
__device__ __half g_aoh[SLEN * QDIM];

// ---------------------------------------------------------------------------
// helpers
// ---------------------------------------------------------------------------
__device__ __forceinline__ uint32_t h2pack(float x, float y) {
    __half2 h = __floats2half2_rn(x, y);
    return *(uint32_t*)&h;
}

__device__ __forceinline__ void mma_f16(float* c, const uint32_t* a,
                                        uint32_t b0, uint32_t b1) {
    asm volatile(
        "mma.sync.aligned.m16n8k16.row.col.f32.f16.f16.f32 "
        "{%0,%1,%2,%3}, {%4,%5,%6,%7}, {%8,%9}, {%0,%1,%2,%3};"
        : "+f"(c[0]), "+f"(c[1]), "+f"(c[2]), "+f"(c[3])
        : "r"(a[0]), "r"(a[1]), "r"(a[2]), "r"(a[3]), "r"(b0), "r"(b1));
}

__device__ __forceinline__ void ldmx4(uint32_t& r0, uint32_t& r1,
                                      uint32_t& r2, uint32_t& r3,
                                      uint32_t addr) {
    asm volatile("ldmatrix.sync.aligned.m8n8.x4.shared.b16 {%0,%1,%2,%3}, [%4];"
                 : "=r"(r0), "=r"(r1), "=r"(r2), "=r"(r3) : "r"(addr));
}

#define CP_ASYNC16(dst, src)                                             \
    asm volatile("cp.async.cg.shared.global [%0], [%1], 16;"             \
                 :: "r"(dst), "l"(src))
#define CP_COMMIT() asm volatile("cp.async.commit_group;")
#define CP_WAIT0() asm volatile("cp.async.wait_group 0;")
#define CP_WAIT1() asm volatile("cp.async.wait_group 1;")
#define CP_WAIT2() asm volatile("cp.async.wait_group 2;")

__device__ __forceinline__ uint32_t smem_u32(const void* p) {
    return (uint32_t)__cvta_generic_to_shared(p);
}

// Q pre-scale: 1/sqrt(64) * log2(e) so exp(x) == exp2(scaled dot)
#define QSCALE 0.1803368801111244f

// ============================================================================
// Fused fp32 -> fp16 conversion of all 5 tensors, 4-way unrolled (MLP=4).
// ============================================================================
#define N4_HS  (SLEN * HIDDEN / 4)
#define N4_WQ  (QDIM * HIDDEN / 4)
#define N4_WKV (KVDIM * HIDDEN / 4)
#define N4_WO  (HIDDEN * QDIM / 4)
#define N4_TOT (N4_HS + N4_WQ + 2 * N4_WKV + N4_WO)

__global__ __launch_bounds__(256) void cvt_all(
    const float4* __restrict__ hs, const float4* __restrict__ wq,
    const float4* __restrict__ wk, const float4* __restrict__ wv,
    const float4* __restrict__ wo)
{
    const int stride = gridDim.x * blockDim.x;
    for (int i0 = blockIdx.x * blockDim.x + threadIdx.x; i0 < N4_TOT;
         i0 += 4 * stride) {
#pragma unroll
        for (int u = 0; u < 4; u++) {
            int i = i0 + u * stride;
            if (i >= N4_TOT) break;
            const float4* src;
            uint2* dst;
            int off = i;
            if (off < N4_HS) {
                src = hs; dst = (uint2*)g_hsh;
            } else if ((off -= N4_HS) < N4_WQ) {
                src = wq; dst = (uint2*)g_wqh;
            } else if ((off -= N4_WQ) < N4_WKV) {
                src = wk; dst = (uint2*)g_wkh;
            } else if ((off -= N4_WKV) < N4_WKV) {
                src = wv; dst = (uint2*)g_wvh;
            } else {
                off -= N4_WKV;
                src = wo; dst = (uint2*)g_woh;
            }
            float4 v = src[off];
            dst[off] = make_uint2(h2pack(v.x, v.y), h2pack(v.z, v.w));
        }
    }
}

// ============================================================================
// fp16 GEMM (R14 proven config): tile 128x128, BK=32, 4-stage cp.async,
// 256 threads, 8 warps each 32x64, ldmatrix fragments. GLD=40 halves.
// Prefetch interleaved: half the next-tile cp.asyncs issue between the two
// kk half-iterations (spreads LSU pressure across the HMMA window).
// ============================================================================
#define GLD 40
#define STG_H (128 * GLD)
#define GEMM_SMEM (4 * 2 * STG_H * 2)  /* 81920 bytes */

// ============================================================================
// Fused QKV GEMM. blockIdx.x: [0,32) Q (pre-scaled), [32,36) K, [36,40) V(T).
// ============================================================================
__global__ __launch_bounds__(256, 2) void qkv_gemm(
    const float* __restrict__ bq, const float* __restrict__ bk,
    const float* __restrict__ bv)
{
    extern __shared__ __half gsm[];

    const int bx = blockIdx.x;
    const int mode = (bx < 32) ? 0 : ((bx < 36) ? 1 : 2);
    const __half* Bg = (mode == 0) ? g_wqh : ((mode == 1) ? g_wkh : g_wvh);
    const float* bias = (mode == 0) ? bq : ((mode == 1) ? bk : bv);
    const int n0 = ((mode == 0) ? bx : ((mode == 1) ? bx - 32 : bx - 36)) * 128;

    const int tid  = threadIdx.x;
    const int lane = tid & 31;
    const int w    = tid >> 5;
    const int wm   = (w & 3) * 32;
    const int wn   = (w >> 2) * 64;
    const int m0   = blockIdx.y * 128;
    const int g    = lane >> 2;
    const int tg   = lane & 3;
    const int l8   = lane & 7;

    const int aoff = (wm + ((lane >> 3) & 1) * 8 + l8) * GLD + (lane >> 4) * 8;
    const int boff = (wn + (lane >> 4) * 8 + l8) * GLD + ((lane >> 3) & 1) * 8;

    float acc[2][8][4];
#pragma unroll
    for (int i = 0; i < 2; i++)
#pragma unroll
        for (int j = 0; j < 8; j++)
#pragma unroll
            for (int q = 0; q < 4; q++) acc[i][j][q] = 0.0f;

    const int lrow = tid >> 2;   // 0..63
    const int lch  = tid & 3;

    // issue one half of a stage's loads (part 0: rows 0-63, part 1: rows 64-127)
    auto issue_half = [&](int t, int part) {
        const int s = t & 3;
        __half* Ab = gsm + s * (2 * STG_H);
        __half* Bb = Ab + STG_H;
        const int k0 = t * 32;
        const int r = lrow + part * 64;
        CP_ASYNC16(smem_u32(&Ab[r * GLD + lch * 8]),
                   g_hsh + (size_t)(m0 + r) * HIDDEN + k0 + lch * 8);
        CP_ASYNC16(smem_u32(&Bb[r * GLD + lch * 8]),
                   Bg + (size_t)(n0 + r) * HIDDEN + k0 + lch * 8);
    };
    auto issue = [&](int t) {
        issue_half(t, 0);
        issue_half(t, 1);
        CP_COMMIT();
    };

    const int KT = HIDDEN / 32;  // 90
    issue(0); issue(1); issue(2);

    for (int t = 0; t < KT; t++) {
        const int rem = KT - 1 - t;
        if (rem >= 2) CP_WAIT2();
        else if (rem == 1) CP_WAIT1();
        else CP_WAIT0();
        __syncthreads();

        const int s = t & 3;
        const __half* Ab = gsm + s * (2 * STG_H);
        const __half* Bb = Ab + STG_H;
        const uint32_t abase = smem_u32(&Ab[aoff]);
        const uint32_t bbase = smem_u32(&Bb[boff]);
        const bool pf = (t + 3 < KT);

#pragma unroll
        for (int kk = 0; kk < 2; kk++) {
            uint32_t a[2][4];
#pragma unroll
            for (int mi = 0; mi < 2; mi++)
                ldmx4(a[mi][0], a[mi][1], a[mi][2], a[mi][3],
                      abase + (mi * 16 * GLD + kk * 16) * 2);
#pragma unroll
            for (int p = 0; p < 4; p++) {
                uint32_t b00, b01, b10, b11;
                ldmx4(b00, b01, b10, b11,
                      bbase + (p * 16 * GLD + kk * 16) * 2);
                mma_f16(acc[0][2 * p],     a[0], b00, b01);
                mma_f16(acc[0][2 * p + 1], a[0], b10, b11);
                mma_f16(acc[1][2 * p],     a[1], b00, b01);
                mma_f16(acc[1][2 * p + 1], a[1], b10, b11);
            }
            if (pf) issue_half(t + 3, kk);   // interleaved prefetch
        }
        if (pf) CP_COMMIT();
    }

    // epilogue -> fp16 outputs (Q pre-scaled by QSCALE)
#pragma unroll
    for (int mi = 0; mi < 2; mi++) {
#pragma unroll
        for (int nj = 0; nj < 8; nj++) {
            const int col = n0 + wn + nj * 8 + 2 * tg;
            const int row = m0 + wm + mi * 16 + g;
            const float b0 = bias[col];
            const float b1 = bias[col + 1];
            float v00 = acc[mi][nj][0] + b0, v01 = acc[mi][nj][1] + b1;
            float v10 = acc[mi][nj][2] + b0, v11 = acc[mi][nj][3] + b1;
            if (mode == 0) {
                v00 *= QSCALE; v01 *= QSCALE; v10 *= QSCALE; v11 *= QSCALE;
                *(uint32_t*)&g_qh[(size_t)row * QDIM + col] = h2pack(v00, v01);
                *(uint32_t*)&g_qh[(size_t)(row + 8) * QDIM + col] = h2pack(v10, v11);
            } else if (mode == 1) {
                *(uint32_t*)&g_kh[(size_t)row * KVDIM + col] = h2pack(v00, v01);
                *(uint32_t*)&g_kh[(size_t)(row + 8) * KVDIM + col] = h2pack(v10, v11);
            } else {
                g_vt[(size_t)col * SLEN + row]           = __float2half_rn(v00);
                g_vt[(size_t)(col + 1) * SLEN + row]     = __float2half_rn(v01);
                g_vt[(size_t)col * SLEN + row + 8]       = __float2half_rn(v10);
                g_vt[(size_t)(col + 1) * SLEN + row + 8] = __float2half_rn(v11);
            }
        }
    }
}

// ============================================================================
// Output projection: fp16 A (g_aoh) x fp16 B (g_woh) -> fp32 out + bias.
// ============================================================================
__global__ __launch_bounds__(256, 2) void wo_gemm(
    const float* __restrict__ bo, float* __restrict__ C)
{
    extern __shared__ __half gsm[];

    const int tid  = threadIdx.x;
    const int lane = tid & 31;
    const int w    = tid >> 5;
    const int wm   = (w & 3) * 32;
    const int wn   = (w >> 2) * 64;
    const int m0   = blockIdx.y * 128;
    const int n0   = blockIdx.x * 128;
    const int g    = lane >> 2;
    const int tg   = lane & 3;
    const int l8   = lane & 7;

    const int aoff = (wm + ((lane >> 3) & 1) * 8 + l8) * GLD + (lane >> 4) * 8;
    const int boff = (wn + (lane >> 4) * 8 + l8) * GLD + ((lane >> 3) & 1) * 8;

    float acc[2][8][4];
#pragma unroll
    for (int i = 0; i < 2; i++)
#pragma unroll
        for (int j = 0; j < 8; j++)
#pragma unroll
            for (int q = 0; q < 4; q++) acc[i][j][q] = 0.0f;

    const int lrow = tid >> 2;
    const int lch  = tid & 3;

    auto issue_half = [&](int t, int part) {
        const int s = t & 3;
        __half* Ab = gsm + s * (2 * STG_H);
        __half* Bb = Ab + STG_H;
        const int k0 = t * 32;
        const int r = lrow + part * 64;
        CP_ASYNC16(smem_u32(&Ab[r * GLD + lch * 8]),
                   g_aoh + (size_t)(m0 + r) * QDIM + k0 + lch * 8);
        const int nrow = n0 + r;
        CP_ASYNC16(smem_u32(&Bb[r * GLD + lch * 8]),
                   g_woh + (size_t)(nrow < HIDDEN ? nrow : 0) * QDIM + k0 + lch * 8);
    };
    auto issue = [&](int t) {
        issue_half(t, 0);
        issue_half(t, 1);
        CP_COMMIT();
    };

    const int KT = QDIM / 32;  // 128
    issue(0); issue(1); issue(2);

    for (int t = 0; t < KT; t++) {
        const int rem = KT - 1 - t;
        if (rem >= 2) CP_WAIT2();
        else if (rem == 1) CP_WAIT1();
        else CP_WAIT0();
        __syncthreads();

        const int s = t & 3;
        const __half* Ab = gsm + s * (2 * STG_H);
        const __half* Bb = Ab + STG_H;
        const uint32_t abase = smem_u32(&Ab[aoff]);
        const uint32_t bbase = smem_u32(&Bb[boff]);
        const bool pf = (t + 3 < KT);

#pragma unroll
        for (int kk = 0; kk < 2; kk++) {
            uint32_t a[2][4];
#pragma unroll
            for (int mi = 0; mi < 2; mi++)
                ldmx4(a[mi][0], a[mi][1], a[mi][2], a[mi][3],
                      abase + (mi * 16 * GLD + kk * 16) * 2);
#pragma unroll
            for (int p = 0; p < 4; p++) {
                uint32_t b00, b01, b10, b11;
                ldmx4(b00, b01, b10, b11,
                      bbase + (p * 16 * GLD + kk * 16) * 2);
                mma_f16(acc[0][2 * p],     a[0], b00, b01);
                mma_f16(acc[0][2 * p + 1], a[0], b10, b11);
                mma_f16(acc[1][2 * p],     a[1], b00, b01);
                mma_f16(acc[1][2 * p + 1], a[1], b10, b11);
            }
            if (pf) issue_half(t + 3, kk);   // interleaved prefetch
        }
        if (pf) CP_COMMIT();
    }

#pragma unroll
    for (int mi = 0; mi < 2; mi++) {
#pragma unroll
        for (int nj = 0; nj < 8; nj++) {
            const int col = n0 + wn + nj * 8 + 2 * tg;
            if (col < HIDDEN) {
                const float b0 = bo[col];
                const float b1 = bo[col + 1];
                const int row = m0 + wm + mi * 16 + g;
                *(float2*)(C + (size_t)row * HIDDEN + col) =
                    make_float2(acc[mi][nj][0] + b0, acc[mi][nj][1] + b1);
                *(float2*)(C + (size_t)(row + 8) * HIDDEN + col) =
                    make_float2(acc[mi][nj][2] + b0, acc[mi][nj][3] + b1);
            }
        }
    }
}

// ============================================================================
// FP16 flash attention (R14 state, best measured): BM=128, 8 warps, no-max
// exp2 softmax, 3-buffer KV pipeline, single barrier/tile, heavy-qb-first,
// diag-only mask, Q pre-scaled by 0.125*log2e.
// ============================================================================
#define FLD 72

__global__ __launch_bounds__(256, 2) void flash_f16()
{
    __shared__ __half Kh[3][64 * FLD];
    __shared__ __half Vh[3][64 * FLD];

    const int h    = blockIdx.y;
    const int qb   = gridDim.x - 1 - blockIdx.x;
    const int kvh  = h >> 3;
    const int tid  = threadIdx.x;
    const int wid  = tid >> 5;
    const int lane = tid & 31;
    const int g    = lane >> 2;
    const int tg   = lane & 3;
    const int l8   = lane & 7;
    const int r0   = qb * 128;
    const int wr   = wid * 16;

    const int qoff  = ((wr & 63) + ((lane >> 3) & 1) * 8 + l8) * FLD + (lane >> 4) * 8;
    const int kvoff = ((lane >> 4) * 8 + l8) * FLD + ((lane >> 3) & 1) * 8;

#pragma unroll
    for (int i = 0; i < 4; i++) {
        const int idx = tid + i * 256;
        const int r = idx >> 3, ch = idx & 7;
        __half* dst = (r < 64) ? &Kh[0][r * FLD + ch * 8]
                               : &Vh[0][(r - 64) * FLD + ch * 8];
        CP_ASYNC16(smem_u32(dst),
                   g_qh + (size_t)(r0 + r) * QDIM + h * HDIM + ch * 8);
    }
    CP_COMMIT();
    CP_WAIT0();
    __syncthreads();

    uint32_t qf[4][4];
    {
        const __half* Qb = (wid < 4) ? &Kh[0][0] : &Vh[0][0];
        const uint32_t qbase = smem_u32(&Qb[qoff]);
#pragma unroll
        for (int kk = 0; kk < 4; kk++)
            ldmx4(qf[kk][0], qf[kk][1], qf[kk][2], qf[kk][3],
                  qbase + kk * 16 * 2);
    }
    __syncthreads();

    const int lr = tid >> 3;
    const int lc = tid & 7;

    auto issue_kv = [&](int j, int buf) {
        const int t0 = j * 64;
#pragma unroll
        for (int i = 0; i < 2; i++) {
            const int r = lr + i * 32;
            CP_ASYNC16(smem_u32(&Kh[buf][r * FLD + lc * 8]),
                       g_kh + (size_t)(t0 + r) * KVDIM + kvh * HDIM + lc * 8);
            CP_ASYNC16(smem_u32(&Vh[buf][r * FLD + lc * 8]),
                       g_vt + (size_t)(kvh * HDIM + r) * SLEN + t0 + lc * 8);
        }
        CP_COMMIT();
    };

    float o[8][4];
#pragma unroll
    for (int nj = 0; nj < 8; nj++)
#pragma unroll
        for (int c = 0; c < 4; c++) o[nj][c] = 0.0f;
    float l_lo = 0.0f, l_hi = 0.0f;

    const int jmax = 2 * qb + 1;
    issue_kv(0, 0);
    if (1 <= jmax) issue_kv(1, 1);

    for (int j = 0; j <= jmax; j++) {
        if (j < jmax) CP_WAIT1();
        else CP_WAIT0();
        __syncthreads();

        if (j + 2 <= jmax) issue_kv(j + 2, (j + 2) % 3);

        const int buf = j % 3;
        const int t0 = j * 64;
        if (t0 <= r0 + wr + 15) {
            const uint32_t kbase = smem_u32(&Kh[buf][kvoff]);
            const uint32_t vbase = smem_u32(&Vh[buf][kvoff]);

            float s[8][4];
#pragma unroll
            for (int nj = 0; nj < 8; nj++)
#pragma unroll
                for (int c = 0; c < 4; c++) s[nj][c] = 0.0f;
#pragma unroll
            for (int kk = 0; kk < 4; kk++) {
#pragma unroll
                for (int p = 0; p < 4; p++) {
                    uint32_t b00, b01, b10, b11;
                    ldmx4(b00, b01, b10, b11,
                          kbase + (p * 16 * FLD + kk * 16) * 2);
                    mma_f16(s[2 * p],     qf[kk], b00, b01);
                    mma_f16(s[2 * p + 1], qf[kk], b10, b11);
                }
            }

            if (t0 + 63 > r0 + wr) {
                const int row_lo = r0 + wr + g;
                const int row_hi = row_lo + 8;
#pragma unroll
                for (int nj = 0; nj < 8; nj++) {
                    const int cb = t0 + nj * 8 + 2 * tg;
                    if (cb     > row_lo) s[nj][0] = -1e30f;
                    if (cb + 1 > row_lo) s[nj][1] = -1e30f;
                    if (cb     > row_hi) s[nj][2] = -1e30f;
                    if (cb + 1 > row_hi) s[nj][3] = -1e30f;
                }
            }

            float sum_lo = 0.0f, sum_hi = 0.0f;
#pragma unroll
            for (int nj = 0; nj < 8; nj++) {
                s[nj][0] = exp2f(s[nj][0]);
                s[nj][1] = exp2f(s[nj][1]);
                s[nj][2] = exp2f(s[nj][2]);
                s[nj][3] = exp2f(s[nj][3]);
                sum_lo += s[nj][0] + s[nj][1];
                sum_hi += s[nj][2] + s[nj][3];
            }
            l_lo += sum_lo;
            l_hi += sum_hi;

#pragma unroll
            for (int kk = 0; kk < 4; kk++) {
                uint32_t pa[4];
                pa[0] = h2pack(s[2 * kk][0],     s[2 * kk][1]);
                pa[1] = h2pack(s[2 * kk][2],     s[2 * kk][3]);
                pa[2] = h2pack(s[2 * kk + 1][0], s[2 * kk + 1][1]);
                pa[3] = h2pack(s[2 * kk + 1][2], s[2 * kk + 1][3]);
#pragma unroll
                for (int p = 0; p < 4; p++) {
                    uint32_t b00, b01, b10, b11;
                    ldmx4(b00, b01, b10, b11,
                          vbase + (p * 16 * FLD + kk * 16) * 2);
                    mma_f16(o[2 * p],     pa, b00, b01);
                    mma_f16(o[2 * p + 1], pa, b10, b11);
                }
            }
        }
    }

    l_lo += __shfl_xor_sync(0xffffffffu, l_lo, 1);
    l_lo += __shfl_xor_sync(0xffffffffu, l_lo, 2);
    l_hi += __shfl_xor_sync(0xffffffffu, l_hi, 1);
    l_hi += __shfl_xor_sync(0xffffffffu, l_hi, 2);
    const float inv_lo = 1.0f / l_lo;
    const float inv_hi = 1.0f / l_hi;
#pragma unroll
    for (int nj = 0; nj < 8; nj++) {
        const int col = h * HDIM + nj * 8 + 2 * tg;
        *(uint32_t*)&g_aoh[(size_t)(r0 + wr + g) * QDIM + col] =
            h2pack(o[nj][0] * inv_lo, o[nj][1] * inv_lo);
        *(uint32_t*)&g_aoh[(size_t)(r0 + wr + g + 8) * QDIM + col] =
            h2pack(o[nj][2] * inv_hi, o[nj][3] * inv_hi);
    }
}

// ============================================================================
// launch
// ============================================================================
extern "C" void kernel_launch(void* const* d_in, const int* in_sizes, int n_in,
                              void* d_out, int out_size)
{
    (void)in_sizes; (void)n_in; (void)out_size;
    const float* hs = (const float*)d_in[0];
    const float* Wq = (const float*)d_in[2];
    const float* bq = (const float*)d_in[3];
    const float* Wk = (const float*)d_in[4];
    const float* bk = (const float*)d_in[5];
    const float* Wv = (const float*)d_in[6];
    const float* bv = (const float*)d_in[7];
    const float* Wo = (const float*)d_in[8];
    const float* bo = (const float*)d_in[9];
    float* out = (float*)d_out;

    static bool attr_set = false;
    if (!attr_set) {
        cudaFuncSetAttribute(qkv_gemm,
                             cudaFuncAttributeMaxDynamicSharedMemorySize, GEMM_SMEM);
        cudaFuncSetAttribute(wo_gemm,
                             cudaFuncAttributeMaxDynamicSharedMemorySize, GEMM_SMEM);
        attr_set = true;
    }

    cvt_all<<<2048, 256>>>((const float4*)hs, (const float4*)Wq,
                           (const float4*)Wk, (const float4*)Wv,
                           (const float4*)Wo);
    qkv_gemm<<<dim3(40, SLEN / 128), 256, GEMM_SMEM>>>(bq, bk, bv);
    flash_f16<<<dim3(SLEN / 128, NHEADS), 256>>>();
    wo_gemm<<<dim3((HIDDEN + 127) / 128, SLEN / 128), 256, GEMM_SMEM>>>(bo, out);
}